// round 1
// baseline (speedup 1.0000x reference)
#include <cuda_runtime.h>
#include <math.h>

#define CB  32
#define CNS 4096
#define CD  256
#define CH  4
#define CDH 64
#define CL  6
#define CNQ 512
#define CNK 1024
#define SCALE_F 0.125f   // 1/sqrt(64)

// ------------------------- scratch (device globals; no allocs) -------------
__device__ float g_upd[CB*CNS*CD];   // working copy of update_tensor
__device__ float g_q  [CB*CNQ*CD];
__device__ float g_k  [CB*CNK*CD];
__device__ float g_Qp [CB*CNQ*CD];
__device__ float g_Kp [CB*CNK*CD];
__device__ float g_Vp [CB*CNK*CD];
__device__ float g_ctx[CB*CNQ*CD];
__device__ float g_h  [CB*CNQ*CD];
__device__ float g_t1 [CB*CNQ*CD];
__device__ float g_t2 [CB*CNQ*CD];

// ------------------------- helpers ----------------------------------------
__device__ __forceinline__ float gelu_tanh(float x){
    // jax.nn.gelu default (approximate=True)
    float x3 = x*x*x;
    float t  = tanhf(0.7978845608028654f * (x + 0.044715f * x3));
    return 0.5f * x * (1.0f + t);
}

// ------------------------- init copy ---------------------------------------
__global__ void k_copy_upd(const float4* __restrict__ src){
    size_t i = (size_t)blockIdx.x * blockDim.x + threadIdx.x;
    ((float4*)g_upd)[i] = src[i];
}

// ------------------------- gather + LayerNorm ------------------------------
// out[row] = LN(emb[idx[p]] + upd[b, idx[p], :]) ; row = b*N + p ; 256 thr/row
__global__ void k_gather_ln(const float* __restrict__ upd,
                            const float* __restrict__ emb,
                            const int*   __restrict__ idx,
                            const float* __restrict__ sc,
                            const float* __restrict__ bi,
                            float* __restrict__ out, int N){
    __shared__ float sbuf[16];
    int row = blockIdx.x;
    int b = row / N, p = row - b*N;
    int node = idx[p];
    int t = threadIdx.x;
    float x = emb[(size_t)node*CD + t] + upd[((size_t)b*CNS + node)*CD + t];
    float s1 = x, s2 = x*x;
    #pragma unroll
    for(int o=16;o>0;o>>=1){
        s1 += __shfl_xor_sync(0xffffffffu, s1, o);
        s2 += __shfl_xor_sync(0xffffffffu, s2, o);
    }
    if((t&31)==0){ sbuf[t>>5]=s1; sbuf[8+(t>>5)]=s2; }
    __syncthreads();
    s1=0.f; s2=0.f;
    #pragma unroll
    for(int i=0;i<8;i++){ s1+=sbuf[i]; s2+=sbuf[8+i]; }
    float mean = s1 * (1.0f/CD);
    float var  = s2 * (1.0f/CD) - mean*mean;
    float rstd = rsqrtf(var + 1e-5f);
    out[(size_t)row*CD + t] = (x-mean)*rstd*sc[t] + bi[t];
}

// ------------------------- plain row LayerNorm -----------------------------
__global__ void k_ln(const float* __restrict__ in,
                     const float* __restrict__ sc,
                     const float* __restrict__ bi,
                     float* __restrict__ out){
    __shared__ float sbuf[16];
    int row = blockIdx.x;
    int t = threadIdx.x;
    float x = in[(size_t)row*CD + t];
    float s1 = x, s2 = x*x;
    #pragma unroll
    for(int o=16;o>0;o>>=1){
        s1 += __shfl_xor_sync(0xffffffffu, s1, o);
        s2 += __shfl_xor_sync(0xffffffffu, s2, o);
    }
    if((t&31)==0){ sbuf[t>>5]=s1; sbuf[8+(t>>5)]=s2; }
    __syncthreads();
    s1=0.f; s2=0.f;
    #pragma unroll
    for(int i=0;i<8;i++){ s1+=sbuf[i]; s2+=sbuf[8+i]; }
    float mean = s1 * (1.0f/CD);
    float var  = s2 * (1.0f/CD) - mean*mean;
    float rstd = rsqrtf(var + 1e-5f);
    out[(size_t)row*CD + t] = (x-mean)*rstd*sc[t] + bi[t];
}

// ------------------------- SGEMM: C[M,256] = A[M,256] @ W[256,256] ---------
// BM=128 BN=64 BK=16, 256 threads, 8x4 micro-tile. act: 0=none, 1=gelu.
__global__ void __launch_bounds__(256)
k_gemm(const float* __restrict__ A, const float* __restrict__ W,
       const float* __restrict__ bias, float* __restrict__ C, int act){
    __shared__ float As[16][132];   // transposed A tile, padded (132*4B % 16B == 0)
    __shared__ float Bs[16][64];
    int tid = threadIdx.x;
    int tx = tid & 15, ty = tid >> 4;
    int bm0 = blockIdx.x * 128;
    int bn0 = blockIdx.y * 64;
    const float* Ab = A + (size_t)bm0 * CD;

    float acc[8][4];
    #pragma unroll
    for(int i=0;i<8;i++)
        #pragma unroll
        for(int j=0;j<4;j++) acc[i][j]=0.f;

    for(int k0=0;k0<CD;k0+=16){
        // load A tile 128x16 (transposed into As[k][m])
        #pragma unroll
        for(int i=0;i<8;i++){
            int lin = tid + i*256;
            int m = lin >> 4, kk = lin & 15;
            As[kk][m] = Ab[(size_t)m*CD + k0 + kk];
        }
        // load B tile 16x64 (one float4 per thread)
        {
            int kk = tid >> 4, n4 = tid & 15;
            *(float4*)&Bs[kk][n4*4] =
                *(const float4*)&W[(size_t)(k0+kk)*CD + bn0 + n4*4];
        }
        __syncthreads();
        #pragma unroll
        for(int kk=0;kk<16;kk++){
            float4 a0 = *(float4*)&As[kk][ty*8];
            float4 a1 = *(float4*)&As[kk][ty*8+4];
            float4 b0 = *(float4*)&Bs[kk][tx*4];
            float a[8] = {a0.x,a0.y,a0.z,a0.w,a1.x,a1.y,a1.z,a1.w};
            float bb[4] = {b0.x,b0.y,b0.z,b0.w};
            #pragma unroll
            for(int i=0;i<8;i++)
                #pragma unroll
                for(int j=0;j<4;j++) acc[i][j] += a[i]*bb[j];
        }
        __syncthreads();
    }
    // epilogue
    float bv[4] = {0.f,0.f,0.f,0.f};
    if(bias){
        float4 b4 = *(const float4*)&bias[bn0 + tx*4];
        bv[0]=b4.x; bv[1]=b4.y; bv[2]=b4.z; bv[3]=b4.w;
    }
    #pragma unroll
    for(int i=0;i<8;i++){
        int m = bm0 + ty*8 + i;
        float4 r;
        float* rp = &r.x;
        #pragma unroll
        for(int j=0;j<4;j++){
            float v = acc[i][j] + bv[j];
            if(act==1) v = gelu_tanh(v);
            rp[j] = v;
        }
        *(float4*)&C[(size_t)m*CD + bn0 + tx*4] = r;
    }
}

// ------------------------- attention (flash-style, fp32) -------------------
// grid (NQ/8, H, B), 256 threads = 8 warps; warp w handles q = bx*8+w.
// Lane-per-key scoring on 32-key smem tiles; online softmax; shfl-broadcast PV.
__global__ void __launch_bounds__(256)
k_attn(const float* __restrict__ Q, const float* __restrict__ K,
       const float* __restrict__ V, const float* __restrict__ mask,
       float* __restrict__ ctx){
    __shared__ float Kt[32][68];   // 68*4B=272B rows: 16B aligned, conflict-free f4
    __shared__ float Vt[32][68];
    __shared__ float qs[8][68];
    int tid = threadIdx.x, w = tid>>5, lane = tid&31;
    int b = blockIdx.z, h = blockIdx.y;
    int q = blockIdx.x*8 + w;

    const float* qrow = Q + ((size_t)(b*CNQ + q))*CD + h*CDH;
    float2 qv = *(const float2*)&qrow[lane*2];
    qs[w][lane*2]   = qv.x;
    qs[w][lane*2+1] = qv.y;
    __syncwarp();

    float   mrun  = -INFINITY;
    float   denom = 0.f;
    float2  acc   = make_float2(0.f, 0.f);

    const float* Kb   = K + ((size_t)b*CNK)*CD + h*CDH;
    const float* Vb   = V + ((size_t)b*CNK)*CD + h*CDH;
    const float* mrow = mask + (size_t)q*CNK;

    for(int k0=0;k0<CNK;k0+=32){
        // cooperative load of 32x64 K and V tiles
        #pragma unroll
        for(int i=0;i<2;i++){
            int f = tid + i*256;
            int r = f >> 4, c4 = f & 15;
            *(float4*)&Kt[r][c4*4] = *(const float4*)&Kb[(size_t)(k0+r)*CD + c4*4];
            *(float4*)&Vt[r][c4*4] = *(const float4*)&Vb[(size_t)(k0+r)*CD + c4*4];
        }
        __syncthreads();

        // score for key (k0+lane): 64-dim dot, 4 partial chains
        float4 ps4 = make_float4(0.f,0.f,0.f,0.f);
        #pragma unroll
        for(int d4=0; d4<16; d4++){
            float4 kk4 = *(float4*)&Kt[lane][d4*4];
            float4 qq4 = *(float4*)&qs[w][d4*4];
            ps4.x += qq4.x*kk4.x; ps4.y += qq4.y*kk4.y;
            ps4.z += qq4.z*kk4.z; ps4.w += qq4.w*kk4.w;
        }
        float s = (ps4.x+ps4.y)+(ps4.z+ps4.w);
        float mval = mrow[k0 + lane];
        s = (mval > 0.5f) ? s*SCALE_F : -1e9f;

        // online softmax
        float tm = s;
        #pragma unroll
        for(int o=16;o>0;o>>=1) tm = fmaxf(tm, __shfl_xor_sync(0xffffffffu, tm, o));
        float mn    = fmaxf(mrun, tm);
        float alpha = __expf(mrun - mn);
        float p     = __expf(s - mn);
        float psum  = p;
        #pragma unroll
        for(int o=16;o>0;o>>=1) psum += __shfl_xor_sync(0xffffffffu, psum, o);
        denom = denom*alpha + psum;
        mrun  = mn;
        acc.x *= alpha; acc.y *= alpha;

        // PV accumulation: broadcast p per key, lanes own 2 dims
        #pragma unroll
        for(int ki=0;ki<32;ki++){
            float pk = __shfl_sync(0xffffffffu, p, ki);
            float2 v = *(float2*)&Vt[ki][lane*2];
            acc.x += pk*v.x;
            acc.y += pk*v.y;
        }
        __syncthreads();
    }
    float inv = 1.0f/denom;
    float2 o  = make_float2(acc.x*inv, acc.y*inv);
    *(float2*)&ctx[((size_t)(b*CNQ+q))*CD + h*CDH + lane*2] = o;
}

// ------------------------- h+ffn, double LN, scatter-add -------------------
__global__ void k_final(const float* __restrict__ h, const float* __restrict__ t2,
                        const float* __restrict__ os, const float* __restrict__ ob,
                        const float* __restrict__ es, const float* __restrict__ eb,
                        const int*   __restrict__ qidx,
                        float* __restrict__ upd, float* __restrict__ outp){
    __shared__ float sbuf[16];
    int row = blockIdx.x;
    int b = row >> 9, p = row & (CNQ-1);
    int t = threadIdx.x;
    float x = h[(size_t)row*CD + t] + t2[(size_t)row*CD + t];

    // LN outer
    float s1 = x, s2 = x*x;
    #pragma unroll
    for(int o=16;o>0;o>>=1){
        s1 += __shfl_xor_sync(0xffffffffu, s1, o);
        s2 += __shfl_xor_sync(0xffffffffu, s2, o);
    }
    if((t&31)==0){ sbuf[t>>5]=s1; sbuf[8+(t>>5)]=s2; }
    __syncthreads();
    s1=0.f; s2=0.f;
    #pragma unroll
    for(int i=0;i<8;i++){ s1+=sbuf[i]; s2+=sbuf[8+i]; }
    float mean = s1*(1.0f/CD);
    float var  = s2*(1.0f/CD) - mean*mean;
    float rstd = rsqrtf(var + 1e-5f);
    float y = (x-mean)*rstd*os[t] + ob[t];
    __syncthreads();

    // LN eff
    s1 = y; s2 = y*y;
    #pragma unroll
    for(int o=16;o>0;o>>=1){
        s1 += __shfl_xor_sync(0xffffffffu, s1, o);
        s2 += __shfl_xor_sync(0xffffffffu, s2, o);
    }
    if((t&31)==0){ sbuf[t>>5]=s1; sbuf[8+(t>>5)]=s2; }
    __syncthreads();
    s1=0.f; s2=0.f;
    #pragma unroll
    for(int i=0;i<8;i++){ s1+=sbuf[i]; s2+=sbuf[8+i]; }
    float mean2 = s1*(1.0f/CD);
    float var2  = s2*(1.0f/CD) - mean2*mean2;
    float rstd2 = rsqrtf(var2 + 1e-5f);
    float res = (y-mean2)*rstd2*es[t] + eb[t];

    int node = qidx[p];
    size_t off = ((size_t)(b*CNS + node))*CD + t;
    atomicAdd(&upd[off],  res);
    atomicAdd(&outp[off], res);
}

// ------------------------- launch ------------------------------------------
extern "C" void kernel_launch(void* const* d_in, const int* in_sizes, int n_in,
                              void* d_out, int out_size){
    const float* in_upd  = (const float*)d_in[0];
    const float* emb     = (const float*)d_in[1];
    const float* maskL   = (const float*)d_in[2];
    const float* Wq      = (const float*)d_in[3];
    const float* Wk      = (const float*)d_in[4];
    const float* Wv      = (const float*)d_in[5];
    const float* Wo      = (const float*)d_in[6];
    const float* W1      = (const float*)d_in[7];
    const float* b1      = (const float*)d_in[8];
    const float* W2      = (const float*)d_in[9];
    const float* b2      = (const float*)d_in[10];
    const float* sys_s   = (const float*)d_in[11];
    const float* sys_b   = (const float*)d_in[12];
    const float* eff_s   = (const float*)d_in[13];
    const float* eff_b   = (const float*)d_in[14];
    const float* in_s    = (const float*)d_in[15];
    const float* in_b    = (const float*)d_in[16];
    const float* out_s   = (const float*)d_in[17];
    const float* out_b   = (const float*)d_in[18];
    const int*   qidxL   = (const int*)d_in[19];
    const int*   kidxL   = (const int*)d_in[20];
    float* outp = (float*)d_out;

    float *upd,*qb,*kb,*Qb,*Kb,*Vb,*ctx,*hb,*t1,*t2;
    cudaGetSymbolAddress((void**)&upd, g_upd);
    cudaGetSymbolAddress((void**)&qb,  g_q);
    cudaGetSymbolAddress((void**)&kb,  g_k);
    cudaGetSymbolAddress((void**)&Qb,  g_Qp);
    cudaGetSymbolAddress((void**)&Kb,  g_Kp);
    cudaGetSymbolAddress((void**)&Vb,  g_Vp);
    cudaGetSymbolAddress((void**)&ctx, g_ctx);
    cudaGetSymbolAddress((void**)&hb,  g_h);
    cudaGetSymbolAddress((void**)&t1,  g_t1);
    cudaGetSymbolAddress((void**)&t2,  g_t2);

    cudaMemsetAsync(d_out, 0, (size_t)out_size * sizeof(float));
    k_copy_upd<<<(CB*CNS*CD/4)/256, 256>>>((const float4*)in_upd);

    for(int l=0;l<CL;l++){
        const int*   qi  = qidxL + l*CNQ;
        const int*   ki  = kidxL + l*CNK;
        const float* msk = maskL + (size_t)l*CNQ*CNK;

        k_gather_ln<<<CB*CNQ, 256>>>(upd, emb, qi, sys_s, sys_b, qb, CNQ);
        k_gather_ln<<<CB*CNK, 256>>>(upd, emb, ki, sys_s, sys_b, kb, CNK);

        k_gemm<<<dim3(CB*CNQ/128, 4), 256>>>(qb, Wq, nullptr, Qb, 0);
        k_gemm<<<dim3(CB*CNK/128, 4), 256>>>(kb, Wk, nullptr, Kb, 0);
        k_gemm<<<dim3(CB*CNK/128, 4), 256>>>(kb, Wv, nullptr, Vb, 0);

        k_attn<<<dim3(CNQ/8, CH, CB), 256>>>(Qb, Kb, Vb, msk, ctx);

        k_gemm<<<dim3(CB*CNQ/128, 4), 256>>>(ctx, Wo, nullptr, t1, 0);
        k_ln  <<<CB*CNQ, 256>>>(t1, in_s, in_b, hb);

        k_gemm<<<dim3(CB*CNQ/128, 4), 256>>>(hb, W1, b1, t1, 1);   // gelu
        k_gemm<<<dim3(CB*CNQ/128, 4), 256>>>(t1, W2, b2, t2, 0);

        k_final<<<CB*CNQ, 256>>>(hb, t2, out_s, out_b, eff_s, eff_b,
                                 qi, upd, outp);
    }
}